// round 9
// baseline (speedup 1.0000x reference)
#include <cuda_runtime.h>
#include <cstdint>
#include <cfloat>

// Problem constants
#define BB 32
#define KK 5
#define TT 12
#define VV 50257
#define HH 512
#define NBEAMS (BB*KK)           // 160
#define NPART 8                  // v-partitions per batch row
#define PERV ((VV + NPART - 1) / NPART)   // 6283
#define TPB_TOPK 512

// Output layout: ONE f32 buffer, outputs cast to f32, concatenated in
// reference return order (element offsets). Verified: rel_err == 0.
#define OFF_SEQ   ((size_t)0)                         // 32*5*13 = 2080
#define OFF_BSLP  ((size_t)2080)
#define OFF_SUM   (OFF_BSLP + (size_t)BB*KK*13*VV)    // 104536640
#define OFF_STATE (OFF_SUM + (size_t)NBEAMS)          // 104536800 (mod 4 == 0)

#define NROWS_BSLP (BB*KK*(TT+1))   // 2080
#define NROWS_STATE (2*NBEAMS)      // 320

// Scratch (static device globals; no allocation)
__device__ float g_part_val[BB * NPART * 5];
__device__ int   g_part_idx[BB * NPART * 5];
__device__ int   g_beam_ix[NBEAMS];
__device__ unsigned int g_done[BB];   // zero-init; reset after each use

__device__ __forceinline__ bool better(float va, int ia, float vb, int ib) {
    return (va > vb) || (va == vb && ia < ib);
}

// Unsorted 5-slot pool with tracked worst. Replace-worst on accept.
struct Pool5 {
    float qv[5]; int qi[5];
    float wv; int wi; int wslot;
    __device__ __forceinline__ void init() {
#pragma unroll
        for (int j = 0; j < 5; j++) { qv[j] = -FLT_MAX; qi[j] = 0x7FFFFFFF; }
        wv = -FLT_MAX; wi = 0x7FFFFFFF; wslot = 0;
    }
    __device__ __forceinline__ void recompute_worst() {
        wv = qv[0]; wi = qi[0]; wslot = 0;
#pragma unroll
        for (int j = 1; j < 5; j++) {
            if (qv[j] < wv || (qv[j] == wv && qi[j] > wi)) {
                wv = qv[j]; wi = qi[j]; wslot = j;
            }
        }
    }
    __device__ __forceinline__ void accept(float val, int idx) {
        if (better(val, idx, wv, wi)) {
#pragma unroll
            for (int j = 0; j < 5; j++)
                if (wslot == j) { qv[j] = val; qi[j] = idx; }
            recompute_worst();
        }
    }
};

// ---------------------------------------------------------------------------
// Kernel 1: topk partials + fused final merge.
// grid (NPART, BB), 512 thr. float4 scan aligned in ABSOLUTE offsets
// (logprobs base is >=256B aligned; row bases are not, K*V odd).
// Cheap gate: bs[k] + max4(x) >= worst  (exact; FADD monotone; ties -> slow).
// ---------------------------------------------------------------------------
__global__ __launch_bounds__(TPB_TOPK) void topk_kernel(
    const float* __restrict__ logprobs,   // (160, V)
    const float* __restrict__ bsum,       // (32, 5)
    const int*   __restrict__ beam_seq,   // (32,5,12) int32
    float* __restrict__ out)
{
    const int b       = blockIdx.y;
    const int part    = blockIdx.x;
    const int tid     = threadIdx.x;
    const int lane    = tid & 31;
    const int v_start = part * PERV;
    const int v_end   = min(v_start + PERV, VV);
    const int rowbase = b * KK * VV;

    float bs[KK];
#pragma unroll
    for (int k = 0; k < KK; k++) bs[k] = bsum[b * KK + k];

    Pool5 P; P.init();

    // Per-k aligned scan windows (absolute element offsets into logprobs).
    int s_k[KK], ng[KK];
    int ngmax = 0;
#pragma unroll
    for (int k = 0; k < KK; k++) {
        int a0 = rowbase + k * VV + v_start;
        int a1 = rowbase + k * VV + v_end;
        int s  = (a0 + 3) & ~3;
        int e  = a1 & ~3;
        s_k[k] = s;
        ng[k]  = (e - s) >> 2;
        ngmax  = max(ngmax, ng[k]);
    }

    // Head/tail scalars (<=3 each per k): threads 0..4 handle row k=tid.
    if (tid < KK) {
        int k = tid;
        int a0 = rowbase + k * VV + v_start;
        int a1 = rowbase + k * VV + v_end;
        for (int o = a0; o < s_k[k]; o++)
            P.accept(bs[k] + logprobs[o], o - rowbase);
        for (int o = s_k[k] + 4 * ng[k]; o < a1; o++)
            P.accept(bs[k] + logprobs[o], o - rowbase);
    }

    for (int g0 = 0; g0 < ngmax; g0 += TPB_TOPK) {
        const int g = g0 + tid;
        float4 x[KK];
#pragma unroll
        for (int k = 0; k < KK; k++) {
            if (g < ng[k]) x[k] = *reinterpret_cast<const float4*>(logprobs + s_k[k] + 4 * g);
            else x[k] = make_float4(-FLT_MAX, -FLT_MAX, -FLT_MAX, -FLT_MAX);
        }
#pragma unroll
        for (int k = 0; k < KK; k++) {
            float m = fmaxf(fmaxf(x[k].x, x[k].y), fmaxf(x[k].z, x[k].w));
            if (g < ng[k] && bs[k] + m >= P.wv) {
                const int base = s_k[k] + 4 * g - rowbase;   // == k*VV + v
                P.accept(bs[k] + x[k].x, base + 0);
                P.accept(bs[k] + x[k].y, base + 1);
                P.accept(bs[k] + x[k].z, base + 2);
                P.accept(bs[k] + x[k].w, base + 3);
            }
        }
    }

    // Sort the 5 slots descending (better-first) via a 9-comparator network.
    float tv[5]; int ti[5];
#pragma unroll
    for (int j = 0; j < 5; j++) { tv[j] = P.qv[j]; ti[j] = P.qi[j]; }
#define CSWAP(a, bq) { if (better(tv[bq], ti[bq], tv[a], ti[a])) { \
        float fv = tv[a]; tv[a] = tv[bq]; tv[bq] = fv; \
        int   iv = ti[a]; ti[a] = ti[bq]; ti[bq] = iv; } }
    CSWAP(0,1) CSWAP(3,4) CSWAP(2,4) CSWAP(2,3) CSWAP(0,3)
    CSWAP(0,2) CSWAP(1,4) CSWAP(1,3) CSWAP(1,2)
#undef CSWAP

    // Block-level merge tree of 512 sorted 5-lists.
    __shared__ float sv[TPB_TOPK * 5];
    __shared__ int   si[TPB_TOPK * 5];
#pragma unroll
    for (int j = 0; j < 5; j++) { sv[tid*5+j] = tv[j]; si[tid*5+j] = ti[j]; }
    __syncthreads();

    for (int s = TPB_TOPK / 2; s > 0; s >>= 1) {
        if (tid < s) {
            float mv[5]; int mi[5];
            int pa = 0, pb = 0;
            const int A = tid * 5, Bo = (tid + s) * 5;
#pragma unroll
            for (int j = 0; j < 5; j++) {
                if (better(sv[A+pa], si[A+pa], sv[Bo+pb], si[Bo+pb])) {
                    mv[j] = sv[A+pa]; mi[j] = si[A+pa]; pa++;
                } else {
                    mv[j] = sv[Bo+pb]; mi[j] = si[Bo+pb]; pb++;
                }
            }
#pragma unroll
            for (int j = 0; j < 5; j++) { sv[A+j] = mv[j]; si[A+j] = mi[j]; }
        }
        __syncthreads();
    }

    __shared__ unsigned int s_isLast;
    if (tid == 0) {
        const int base = (b * NPART + part) * 5;
#pragma unroll
        for (int j = 0; j < 5; j++) {
            g_part_val[base + j] = sv[j];
            g_part_idx[base + j] = si[j];
        }
        __threadfence();
        unsigned int old = atomicAdd(&g_done[b], 1u);
        s_isLast = (old == NPART - 1) ? 1u : 0u;
    }
    __syncthreads();

    // Last block for this row: merge 8 partial lists (lanes 0..7), emit.
    if (s_isLast && tid < 32) {
        __threadfence();   // acquire: partials of all blocks visible
        float v0 = -FLT_MAX, v1 = -FLT_MAX, v2 = -FLT_MAX, v3 = -FLT_MAX, v4 = -FLT_MAX;
        int   i0 = 0x7FFFFFFF, i1 = 0x7FFFFFFF, i2 = 0x7FFFFFFF, i3 = 0x7FFFFFFF, i4 = 0x7FFFFFFF;
        if (lane < NPART) {
            const int base = (b * NPART + lane) * 5;
            v0 = g_part_val[base+0]; i0 = g_part_idx[base+0];
            v1 = g_part_val[base+1]; i1 = g_part_idx[base+1];
            v2 = g_part_val[base+2]; i2 = g_part_idx[base+2];
            v3 = g_part_val[base+3]; i3 = g_part_idx[base+3];
            v4 = g_part_val[base+4]; i4 = g_part_idx[base+4];
        }

        int win_bi[5], win_sel[5];
        float win_v[5];
#pragma unroll
        for (int r = 0; r < 5; r++) {
            float bv = v0; int bi = i0;
#pragma unroll
            for (int s = 16; s > 0; s >>= 1) {
                float ov = __shfl_xor_sync(0xFFFFFFFF, bv, s);
                int   oi = __shfl_xor_sync(0xFFFFFFFF, bi, s);
                if (better(ov, oi, bv, bi)) { bv = ov; bi = oi; }
            }
            if (i0 == bi && lane < NPART) {   // flat indices unique
                v0 = v1; i0 = i1; v1 = v2; i1 = i2;
                v2 = v3; i2 = i3; v3 = v4; i3 = i4;
                v4 = -FLT_MAX; i4 = 0x7FFFFFFF;
            }
            win_v[r]   = bv;
            win_bi[r]  = bi / VV;
            win_sel[r] = bi - win_bi[r] * VV;
        }

        if (lane < 5) {
            g_beam_ix[b * KK + lane]     = win_bi[lane];
            out[OFF_SUM + b * KK + lane] = win_v[lane];
        }
        for (int idx = lane; idx < 5 * (TT + 1); idx += 32) {
            int j = idx / (TT + 1);
            int t = idx - j * (TT + 1);
            float val;
            if (t < TT) val = (float)beam_seq[(size_t)(b * KK + win_bi[j]) * TT + t];
            else        val = (float)win_sel[j];
            out[OFF_SEQ + (size_t)(b * KK + j) * (TT + 1) + t] = val;
        }
        if (lane == 0) g_done[b] = 0;   // reset for next graph replay
    }
}

// ---------------------------------------------------------------------------
// Kernel 2: big gather with smem realignment staging + state gather.
// grid (13, 2080 + 320), 256 thr. Aligned LDG.128 -> padded smem -> aligned
// STG.128; no scalar global fallback path.
// ---------------------------------------------------------------------------
#define PAD(i) ((i) + ((i) >> 5))

__global__ __launch_bounds__(256) void gather_big_kernel(
    const float* __restrict__ bslp,    // (32,5,12,V)
    const float* __restrict__ unaug,   // (160,V)
    const float* __restrict__ state,   // (2,160,512)
    float* __restrict__ out)
{
    const int row = blockIdx.y;
    const int tid = threadIdx.x;

    if (row < NROWS_BSLP) {
        const int t   = row % (TT + 1);
        const int bk  = row / (TT + 1);
        const int b   = bk / KK;
        const int bi  = g_beam_ix[bk];

        const float* sbase; size_t soff; long slen;
        if (t < TT) {
            sbase = bslp;
            soff  = ((size_t)(b * KK + bi) * TT + t) * VV;
            slen  = (long)NBEAMS * TT * VV;
        } else {
            sbase = unaug;
            soff  = (size_t)(b * KK + bi) * VV;
            slen  = (long)NBEAMS * VV;
        }

        const size_t dst_off = OFF_BSLP + (size_t)row * VV;
        float* dst = out + dst_off;

        const int lead = (int)((4 - (dst_off & 3)) & 3);
        const int nvec = (VV - lead) >> 2;
        const int tb   = blockIdx.x * 1024;
        const int nv   = min(1024, nvec - tb);

        __shared__ float sm[4233];   // 4100 data + stride-32 padding

        if (nv > 0) {
            const int  E0 = lead + 4 * tb;
            const int  ps = (int)((soff + (size_t)E0) & 3);   // sbase >=256B aligned
            const long g0 = (long)(soff + (size_t)E0) - ps;   // 16B-aligned elem index
            const int  NE = 4 * nv;
            const int  n4 = (NE + ps + 3) >> 2;               // <= 1025

            for (int i = tid; i < n4; i += 256) {
                const long g = g0 + 4 * (long)i;
                float4 v;
                if (g >= 0 && g + 4 <= slen) {
                    v = *reinterpret_cast<const float4*>(sbase + g);
                } else {
                    v.x = (g + 0 >= 0 && g + 0 < slen) ? sbase[g + 0] : 0.0f;
                    v.y = (g + 1 >= 0 && g + 1 < slen) ? sbase[g + 1] : 0.0f;
                    v.z = (g + 2 >= 0 && g + 2 < slen) ? sbase[g + 2] : 0.0f;
                    v.w = (g + 3 >= 0 && g + 3 < slen) ? sbase[g + 3] : 0.0f;
                }
                const int o = 4 * i;
                sm[PAD(o + 0)] = v.x;
                sm[PAD(o + 1)] = v.y;
                sm[PAD(o + 2)] = v.z;
                sm[PAD(o + 3)] = v.w;
            }
            __syncthreads();

#pragma unroll
            for (int j = 0; j < 4; j++) {
                const int tv_ = tb + j * 256 + tid;
                if (tv_ < tb + nv) {
                    int l = 4 * (tv_ - tb) + ps;
                    float4 v;
                    v.x = sm[PAD(l + 0)];
                    v.y = sm[PAD(l + 1)];
                    v.z = sm[PAD(l + 2)];
                    v.w = sm[PAD(l + 3)];
                    *reinterpret_cast<float4*>(dst + lead + 4 * tv_) = v;
                }
            }
        }

        // lead + tail scalars (block 0 only), direct from the row.
        if (blockIdx.x == 0 && tid < 8) {
            const int tail_start = lead + 4 * nvec;
            if (tid < 4) {
                int v = tid;
                if (v < lead) dst[v] = sbase[soff + v];
            } else {
                int v = tail_start + (tid - 4);
                if (v < VV) dst[v] = sbase[soff + v];
            }
        }
    } else {
        if (blockIdx.x != 0) return;
        const int r2 = row - NROWS_BSLP;      // 0..319
        const int s  = r2 / NBEAMS;
        const int j  = r2 - s * NBEAMS;
        const int b  = j / KK;
        const int bi = g_beam_ix[j];

        const float4* src = reinterpret_cast<const float4*>(
            state + (size_t)s * NBEAMS * HH + (size_t)(b * KK + bi) * HH);
        float4* dst = reinterpret_cast<float4*>(
            out + OFF_STATE + (size_t)r2 * HH);
        if (tid < HH / 4)
            dst[tid] = src[tid];
    }
}

// ---------------------------------------------------------------------------
extern "C" void kernel_launch(void* const* d_in, const int* in_sizes, int n_in,
                              void* d_out, int out_size) {
    const float* logprobs = (const float*)d_in[0];       // (160, V)
    const float* unaug    = (const float*)d_in[1];       // (160, V)
    const int*   beam_seq = (const int*)d_in[2];         // (32,5,12) int32
    const float* bslp     = (const float*)d_in[3];       // (32,5,12,V)
    const float* bsum     = (const float*)d_in[4];       // (32,5)
    const float* state    = (const float*)d_in[5];       // (2,160,512)
    // d_in[6] = bdash (=5), hardcoded

    float* out = (float*)d_out;

    {
        dim3 grid(NPART, BB);   // (8, 32) = 256 blocks x 512 threads
        topk_kernel<<<grid, TPB_TOPK>>>(logprobs, bsum, beam_seq, out);
    }
    {
        dim3 grid(13, NROWS_BSLP + NROWS_STATE);
        gather_big_kernel<<<grid, 256>>>(bslp, unaug, state, out);
    }
}

// round 10
// speedup vs baseline: 1.3763x; 1.3763x over previous
#include <cuda_runtime.h>
#include <cstdint>
#include <cfloat>

// Problem constants
#define BB 32
#define KK 5
#define TT 12
#define VV 50257
#define HH 512
#define NBEAMS (BB*KK)           // 160
#define NPART 32                 // v-partitions per batch row
#define PERV ((VV + NPART - 1) / NPART)   // 1571 -> ng<=393 <= 2*256
#define TPB_TOPK 256

// Output layout: ONE f32 buffer, outputs cast to f32, concatenated in
// reference return order (element offsets). Verified: rel_err == 0.
#define OFF_SEQ   ((size_t)0)                         // 32*5*13 = 2080
#define OFF_BSLP  ((size_t)2080)
#define OFF_SUM   (OFF_BSLP + (size_t)BB*KK*13*VV)    // 104536640
#define OFF_STATE (OFF_SUM + (size_t)NBEAMS)          // 104536800 (mod 4 == 0)

#define NROWS_BSLP (BB*KK*(TT+1))   // 2080
#define NROWS_STATE (2*NBEAMS)      // 320

// Scratch (static device globals; no allocation)
__device__ float g_part_val[BB * NPART * 5];
__device__ int   g_part_idx[BB * NPART * 5];
__device__ int   g_beam_ix[NBEAMS];
__device__ unsigned int g_done[BB];   // zero-init; reset after each use

__device__ __forceinline__ bool better(float va, int ia, float vb, int ib) {
    return (va > vb) || (va == vb && ia < ib);
}

__device__ __forceinline__ void insert5(float val, int idx, float tv[5], int ti[5]) {
    if (better(val, idx, tv[4], ti[4])) {
        tv[4] = val; ti[4] = idx;
#pragma unroll
        for (int j = 4; j > 0; j--) {
            if (better(tv[j], ti[j], tv[j-1], ti[j-1])) {
                float fv = tv[j]; tv[j] = tv[j-1]; tv[j-1] = fv;
                int   iv = ti[j]; ti[j] = ti[j-1]; ti[j-1] = iv;
            }
        }
    }
}

// ---------------------------------------------------------------------------
// Kernel 1: exact two-pass topk + fused final merge.
// grid (NPART, BB), 256 thr. Each thread holds <=2 groups x 5 rows of float4
// in registers. Warp threshold T = 5th largest of 32 thread-maxes (provable
// bound). Gate gv = bs[k]+max4 >= T is exact (FADD monotone, same rounding).
// ---------------------------------------------------------------------------
__global__ __launch_bounds__(TPB_TOPK) void topk_kernel(
    const float* __restrict__ logprobs,   // (160, V)
    const float* __restrict__ bsum,       // (32, 5)
    const int*   __restrict__ beam_seq,   // (32,5,12) int32
    float* __restrict__ out)
{
    const int b       = blockIdx.y;
    const int part    = blockIdx.x;
    const int tid     = threadIdx.x;
    const int lane    = tid & 31;
    const int v_start = part * PERV;
    const int v_end   = min(v_start + PERV, VV);
    const int rowbase = b * KK * VV;

    float bs[KK];
#pragma unroll
    for (int k = 0; k < KK; k++) bs[k] = bsum[b * KK + k];

    // Per-k aligned scan windows (absolute element offsets into logprobs;
    // logprobs base >=256B aligned, row bases are NOT since K*V is odd).
    int s_k[KK], ng[KK];
#pragma unroll
    for (int k = 0; k < KK; k++) {
        int a0 = rowbase + k * VV + v_start;
        int a1 = rowbase + k * VV + v_end;
        int s  = (a0 + 3) & ~3;
        s_k[k] = s;
        ng[k]  = ((a1 & ~3) - s) >> 2;   // <= 393
    }

    // ---- Load both groups into registers ----
    const int ga = tid, gb = tid + TPB_TOPK;
    float4 xa[KK], xb[KK];
#pragma unroll
    for (int k = 0; k < KK; k++) {
        xa[k] = (ga < ng[k]) ? *reinterpret_cast<const float4*>(logprobs + s_k[k] + 4 * ga)
                             : make_float4(-FLT_MAX, -FLT_MAX, -FLT_MAX, -FLT_MAX);
        xb[k] = (gb < ng[k]) ? *reinterpret_cast<const float4*>(logprobs + s_k[k] + 4 * gb)
                             : make_float4(-FLT_MAX, -FLT_MAX, -FLT_MAX, -FLT_MAX);
    }

    // ---- Pass 1: group values, thread max ----
    float gva[KK], gvb[KK];
    float tm = -FLT_MAX;
#pragma unroll
    for (int k = 0; k < KK; k++) {
        gva[k] = bs[k] + fmaxf(fmaxf(xa[k].x, xa[k].y), fmaxf(xa[k].z, xa[k].w));
        gvb[k] = bs[k] + fmaxf(fmaxf(xb[k].x, xb[k].y), fmaxf(xb[k].z, xb[k].w));
        if (ga < ng[k]) tm = fmaxf(tm, gva[k]);
        if (gb < ng[k]) tm = fmaxf(tm, gvb[k]);
    }

    // ---- Warp: T = 5th largest of 32 thread maxes ----
    float cur = tm, T = -FLT_MAX;
#pragma unroll
    for (int r = 0; r < 5; r++) {
        float bv = cur; int bl = lane;
#pragma unroll
        for (int s = 16; s > 0; s >>= 1) {
            float ov = __shfl_xor_sync(0xFFFFFFFF, bv, s);
            int   ol = __shfl_xor_sync(0xFFFFFFFF, bl, s);
            if (ov > bv || (ov == bv && ol < bl)) { bv = ov; bl = ol; }
        }
        if (bl == lane) cur = -FLT_MAX;
        T = bv;
    }

    // ---- Pass 2: gated exact inserts ----
    float tv[5]; int ti[5];
#pragma unroll
    for (int j = 0; j < 5; j++) { tv[j] = -FLT_MAX; ti[j] = 0x7FFFFFFF; }

#pragma unroll
    for (int k = 0; k < KK; k++) {
        if (ga < ng[k] && gva[k] >= T) {
            const int base = s_k[k] + 4 * ga - rowbase;   // == k*VV + v
            insert5(bs[k] + xa[k].x, base + 0, tv, ti);
            insert5(bs[k] + xa[k].y, base + 1, tv, ti);
            insert5(bs[k] + xa[k].z, base + 2, tv, ti);
            insert5(bs[k] + xa[k].w, base + 3, tv, ti);
        }
        if (gb < ng[k] && gvb[k] >= T) {
            const int base = s_k[k] + 4 * gb - rowbase;
            insert5(bs[k] + xb[k].x, base + 0, tv, ti);
            insert5(bs[k] + xb[k].y, base + 1, tv, ti);
            insert5(bs[k] + xb[k].z, base + 2, tv, ti);
            insert5(bs[k] + xb[k].w, base + 3, tv, ti);
        }
    }

    // Head/tail scalars (<=3 each per k): threads 0..4 handle row k=tid.
    if (tid < KK) {
        int k = tid;
        int a0 = rowbase + k * VV + v_start;
        int a1 = rowbase + k * VV + v_end;
        for (int o = a0; o < s_k[k]; o++)
            insert5(bs[k] + logprobs[o], o - rowbase, tv, ti);
        for (int o = s_k[k] + 4 * ng[k]; o < a1; o++)
            insert5(bs[k] + logprobs[o], o - rowbase, tv, ti);
    }

    // ---- Block merge tree of 256 sorted 5-lists ----
    __shared__ float sv[TPB_TOPK * 5];
    __shared__ int   si[TPB_TOPK * 5];
#pragma unroll
    for (int j = 0; j < 5; j++) { sv[tid*5+j] = tv[j]; si[tid*5+j] = ti[j]; }
    __syncthreads();

    for (int s = TPB_TOPK / 2; s > 0; s >>= 1) {
        if (tid < s) {
            float mv[5]; int mi[5];
            int pa = 0, pb = 0;
            const int A = tid * 5, Bo = (tid + s) * 5;
#pragma unroll
            for (int j = 0; j < 5; j++) {
                if (better(sv[A+pa], si[A+pa], sv[Bo+pb], si[Bo+pb])) {
                    mv[j] = sv[A+pa]; mi[j] = si[A+pa]; pa++;
                } else {
                    mv[j] = sv[Bo+pb]; mi[j] = si[Bo+pb]; pb++;
                }
            }
#pragma unroll
            for (int j = 0; j < 5; j++) { sv[A+j] = mv[j]; si[A+j] = mi[j]; }
        }
        __syncthreads();
    }

    __shared__ unsigned int s_isLast;
    if (tid == 0) {
        const int base = (b * NPART + part) * 5;
#pragma unroll
        for (int j = 0; j < 5; j++) {
            g_part_val[base + j] = sv[j];
            g_part_idx[base + j] = si[j];
        }
        __threadfence();
        unsigned int old = atomicAdd(&g_done[b], 1u);
        s_isLast = (old == NPART - 1) ? 1u : 0u;
    }
    __syncthreads();

    // Last block for this row: merge 32 partial lists (one per lane), emit.
    if (s_isLast && tid < 32) {
        __threadfence();   // acquire: partials of all blocks visible
        const int base = (b * NPART + lane) * 5;
        float v0 = g_part_val[base+0], v1 = g_part_val[base+1], v2 = g_part_val[base+2],
              v3 = g_part_val[base+3], v4 = g_part_val[base+4];
        int   i0 = g_part_idx[base+0], i1 = g_part_idx[base+1], i2 = g_part_idx[base+2],
              i3 = g_part_idx[base+3], i4 = g_part_idx[base+4];

        int win_bi[5], win_sel[5];
        float win_v[5];
#pragma unroll
        for (int r = 0; r < 5; r++) {
            float bv = v0; int bi = i0;
#pragma unroll
            for (int s = 16; s > 0; s >>= 1) {
                float ov = __shfl_xor_sync(0xFFFFFFFF, bv, s);
                int   oi = __shfl_xor_sync(0xFFFFFFFF, bi, s);
                if (better(ov, oi, bv, bi)) { bv = ov; bi = oi; }
            }
            if (i0 == bi) {   // flat indices unique
                v0 = v1; i0 = i1; v1 = v2; i1 = i2;
                v2 = v3; i2 = i3; v3 = v4; i3 = i4;
                v4 = -FLT_MAX; i4 = 0x7FFFFFFF;
            }
            win_v[r]   = bv;
            win_bi[r]  = bi / VV;
            win_sel[r] = bi - win_bi[r] * VV;
        }

        if (lane < 5) {
            g_beam_ix[b * KK + lane]     = win_bi[lane];
            out[OFF_SUM + b * KK + lane] = win_v[lane];
        }
        for (int idx = lane; idx < 5 * (TT + 1); idx += 32) {
            int j = idx / (TT + 1);
            int t = idx - j * (TT + 1);
            float val;
            if (t < TT) val = (float)beam_seq[(size_t)(b * KK + win_bi[j]) * TT + t];
            else        val = (float)win_sel[j];
            out[OFF_SEQ + (size_t)(b * KK + j) * (TT + 1) + t] = val;
        }
        if (lane == 0) g_done[b] = 0;   // reset for next graph replay
    }
}

// ---------------------------------------------------------------------------
// Kernel 2: big gather via dual aligned LDG.128 + component select (ps is
// row-uniform), plus state gather. grid (13, 2080 + 320), 256 thr.
// ---------------------------------------------------------------------------
__global__ __launch_bounds__(256) void gather_big_kernel(
    const float* __restrict__ bslp,    // (32,5,12,V)
    const float* __restrict__ unaug,   // (160,V)
    const float* __restrict__ state,   // (2,160,512)
    float* __restrict__ out)
{
    const int row = blockIdx.y;
    const int tid = threadIdx.x;

    if (row < NROWS_BSLP) {
        const int t   = row % (TT + 1);
        const int bk  = row / (TT + 1);
        const int b   = bk / KK;
        const int bi  = g_beam_ix[bk];

        const float* sbase; size_t soff; long slen;
        if (t < TT) {
            sbase = bslp;
            soff  = ((size_t)(b * KK + bi) * TT + t) * VV;
            slen  = (long)NBEAMS * TT * VV;
        } else {
            sbase = unaug;
            soff  = (size_t)(b * KK + bi) * VV;
            slen  = (long)NBEAMS * VV;
        }

        const size_t dst_off = OFF_BSLP + (size_t)row * VV;
        float* dst = out + dst_off;

        const int lead = (int)((4 - (dst_off & 3)) & 3);
        const int nvec = (VV - lead) >> 2;
        const int tb   = blockIdx.x * 1024;
        const int nv   = min(1024, nvec - tb);

        if (nv > 0) {
            const int  E0 = lead + 4 * tb;
            const int  ps = (int)((soff + (size_t)E0) & 3);
            const long g0 = (long)(soff + (size_t)E0) - ps;   // 16B-aligned

            if (ps == 0) {
#pragma unroll
                for (int q = 0; q < 4; q++) {
                    const int j = q * 256 + tid;
                    if (j < nv) {
                        const float4 v = *reinterpret_cast<const float4*>(sbase + g0 + 4 * (long)j);
                        *reinterpret_cast<float4*>(dst + lead + 4 * (tb + j)) = v;
                    }
                }
            } else {
#pragma unroll
                for (int q = 0; q < 4; q++) {
                    const int j = q * 256 + tid;
                    if (j < nv) {
                        const long a = g0 + 4 * (long)j;
                        float4 lo, hi;
                        lo = *reinterpret_cast<const float4*>(sbase + a);
                        if (a + 8 <= slen) {
                            hi = *reinterpret_cast<const float4*>(sbase + a + 4);
                        } else {
                            hi.x = (a + 4 < slen) ? sbase[a + 4] : 0.0f;
                            hi.y = (a + 5 < slen) ? sbase[a + 5] : 0.0f;
                            hi.z = (a + 6 < slen) ? sbase[a + 6] : 0.0f;
                            hi.w = 0.0f;
                        }
                        float4 v;
                        if (ps == 1)      v = make_float4(lo.y, lo.z, lo.w, hi.x);
                        else if (ps == 2) v = make_float4(lo.z, lo.w, hi.x, hi.y);
                        else              v = make_float4(lo.w, hi.x, hi.y, hi.z);
                        *reinterpret_cast<float4*>(dst + lead + 4 * (tb + j)) = v;
                    }
                }
            }
        }

        // lead + tail scalars (block 0 only), direct.
        if (blockIdx.x == 0 && tid < 8) {
            const int tail_start = lead + 4 * nvec;
            if (tid < 4) {
                int v = tid;
                if (v < lead) dst[v] = sbase[soff + v];
            } else {
                int v = tail_start + (tid - 4);
                if (v < VV) dst[v] = sbase[soff + v];
            }
        }
    } else {
        if (blockIdx.x != 0) return;
        const int r2 = row - NROWS_BSLP;      // 0..319
        const int s  = r2 / NBEAMS;
        const int j  = r2 - s * NBEAMS;
        const int b  = j / KK;
        const int bi = g_beam_ix[j];

        const float4* src = reinterpret_cast<const float4*>(
            state + (size_t)s * NBEAMS * HH + (size_t)(b * KK + bi) * HH);
        float4* dst = reinterpret_cast<float4*>(
            out + OFF_STATE + (size_t)r2 * HH);
        if (tid < HH / 4)
            dst[tid] = src[tid];
    }
}

// ---------------------------------------------------------------------------
extern "C" void kernel_launch(void* const* d_in, const int* in_sizes, int n_in,
                              void* d_out, int out_size) {
    const float* logprobs = (const float*)d_in[0];       // (160, V)
    const float* unaug    = (const float*)d_in[1];       // (160, V)
    const int*   beam_seq = (const int*)d_in[2];         // (32,5,12) int32
    const float* bslp     = (const float*)d_in[3];       // (32,5,12,V)
    const float* bsum     = (const float*)d_in[4];       // (32,5)
    const float* state    = (const float*)d_in[5];       // (2,160,512)
    // d_in[6] = bdash (=5), hardcoded

    float* out = (float*)d_out;

    {
        dim3 grid(NPART, BB);   // (32, 32) = 1024 blocks
        topk_kernel<<<grid, TPB_TOPK>>>(logprobs, bsum, beam_seq, out);
    }
    {
        dim3 grid(13, NROWS_BSLP + NROWS_STATE);
        gather_big_kernel<<<grid, 256>>>(bslp, unaug, state, out);
    }
}